// round 2
// baseline (speedup 1.0000x reference)
#include <cuda_runtime.h>
#include <math.h>

#define HID 128
#define EB  64          // edges (or nodes) per block
#define STR 132         // padded smem row stride (floats)
#define KC  32          // K-chunk for weight staging
#define TPB 256

// scratch for segment-sum result m_i (N*HID floats, N<=50000)
__device__ float g_mi[6500000];

__global__ void zero_mi_kernel(int n4) {
    int i = blockIdx.x * blockDim.x + threadIdx.x;
    if (i < n4) ((float4*)g_mi)[i] = make_float4(0.f, 0.f, 0.f, 0.f);
}

__device__ __forceinline__ float silu_f(float v) {
    return v / (1.f + __expf(-v));
}

// vectorized global reduction: 4 contiguous f32 adds in one instruction
__device__ __forceinline__ void red_add_v4(float* addr, float a, float b, float c, float d) {
    asm volatile("red.global.add.v4.f32 [%0], {%1, %2, %3, %4};"
                 :: "l"(addr), "f"(a), "f"(b), "f"(c), "f"(d) : "memory");
}

// ---------------------------------------------------------------------------
// Edge kernel: per block of 64 edges, compute
//   m1 = silu([h_s|h_t|d] @ w1 + b1)
//   m2 = silu(m1 @ w2 + b2)
//   g  = sigmoid(m2 @ winf + binf)
//   g_mi[src] += g*m2   (red.v4)
// 256 threads; thread (tx,ty) owns 4 edges x 8 hidden cols in registers.
// ---------------------------------------------------------------------------
__global__ void edge_kernel(const float* __restrict__ h, const float* __restrict__ x,
                            const int* __restrict__ edges,
                            const float* __restrict__ w1, const float* __restrict__ b1,
                            const float* __restrict__ w2, const float* __restrict__ b2,
                            const float* __restrict__ winf, const float* __restrict__ binf,
                            int N, int E) {
    extern __shared__ float sm[];
    float* hs   = sm;                  // EB*STR  : h[src], later m1
    float* ht   = hs + EB * STR;       // EB*STR  : h[dst]
    float* ws   = ht + EB * STR;       // KC*HID  : weight tile
    float* s_gd = ws + KC * HID;       // EB      : dist, later gate
    int*   s_st = (int*)(s_gd + EB);   // EB
    int*   s_en = s_st + EB;           // EB

    const int tid = threadIdx.x;
    const int tx = tid & 15, ty = tid >> 4;
    const int e0 = ty * 4;
    const int j0 = tx * 8;
    const long ebase = (long)blockIdx.x * EB;

    // edge indices + distances
    if (tid < EB) {
        long e = ebase + tid;
        int st = -1, en = -1; float d = 0.f;
        if (e < (long)E) {
            st = edges[2 * e];
            en = edges[2 * e + 1];
            float dx = x[3 * st + 0] - x[3 * en + 0];
            float dy = x[3 * st + 1] - x[3 * en + 1];
            float dz = x[3 * st + 2] - x[3 * en + 2];
            d = sqrtf(dx * dx + dy * dy + dz * dz);
        }
        s_st[tid] = st; s_en[tid] = en; s_gd[tid] = d;
    }
    __syncthreads();

    // gather h rows (float4, L2-resident)
    for (int i = tid; i < EB * 32; i += TPB) {
        int row = i >> 5, c4 = i & 31;
        int r = s_st[row];
        float4 v = make_float4(0.f, 0.f, 0.f, 0.f);
        if (r >= 0) v = ((const float4*)(h + (long)r * HID))[c4];
        ((float4*)(hs + row * STR))[c4] = v;
    }
    for (int i = tid; i < EB * 32; i += TPB) {
        int row = i >> 5, c4 = i & 31;
        int r = s_en[row];
        float4 v = make_float4(0.f, 0.f, 0.f, 0.f);
        if (r >= 0) v = ((const float4*)(h + (long)r * HID))[c4];
        ((float4*)(ht + row * STR))[c4] = v;
    }
    __syncthreads();

    float acc[4][8];
    #pragma unroll
    for (int e = 0; e < 4; e++)
        #pragma unroll
        for (int j = 0; j < 8; j++) acc[e][j] = 0.f;

    // ---- layer 1: k = 0..255 over [h_s | h_t] ----
    for (int kb = 0; kb < 8; ++kb) {
        const float4* wsrc = (const float4*)(w1 + kb * KC * HID);
        for (int i = tid; i < KC * HID / 4; i += TPB) ((float4*)ws)[i] = wsrc[i];
        __syncthreads();
        const float* src = (kb < 4) ? hs : ht;
        const int ks = (kb & 3) * KC;
        #pragma unroll
        for (int k = 0; k < KC; ++k) {
            const float4* wrow = (const float4*)(ws + k * HID);
            float4 bA = wrow[tx * 2], bB = wrow[tx * 2 + 1];
            float bv[8] = {bA.x, bA.y, bA.z, bA.w, bB.x, bB.y, bB.z, bB.w};
            #pragma unroll
            for (int e = 0; e < 4; ++e) {
                float a = src[(e0 + e) * STR + ks + k];
                #pragma unroll
                for (int j = 0; j < 8; ++j) acc[e][j] = fmaf(a, bv[j], acc[e][j]);
            }
        }
        __syncthreads();
    }
    // dist row (k=256) + bias + silu
    {
        float wr[8], bb[8];
        #pragma unroll
        for (int j = 0; j < 8; j++) { wr[j] = w1[256 * HID + j0 + j]; bb[j] = b1[j0 + j]; }
        #pragma unroll
        for (int e = 0; e < 4; e++) {
            float d = s_gd[e0 + e];
            #pragma unroll
            for (int j = 0; j < 8; j++) {
                float v = fmaf(d, wr[j], acc[e][j]) + bb[j];
                acc[e][j] = silu_f(v);
            }
        }
    }
    // stash m1 into hs (hs reads all completed; next __syncthreads orders these
    // writes before the layer-2 reads)
    #pragma unroll
    for (int e = 0; e < 4; e++)
        #pragma unroll
        for (int j = 0; j < 8; j++) hs[(e0 + e) * STR + j0 + j] = acc[e][j];

    // ---- layer 2: m2 = silu(m1 @ w2 + b2) ----
    float m2[4][8];
    #pragma unroll
    for (int e = 0; e < 4; e++)
        #pragma unroll
        for (int j = 0; j < 8; j++) m2[e][j] = 0.f;

    for (int kb = 0; kb < 4; ++kb) {
        const float4* wsrc = (const float4*)(w2 + kb * KC * HID);
        for (int i = tid; i < KC * HID / 4; i += TPB) ((float4*)ws)[i] = wsrc[i];
        __syncthreads();
        const int ks = kb * KC;
        #pragma unroll
        for (int k = 0; k < KC; ++k) {
            const float4* wrow = (const float4*)(ws + k * HID);
            float4 bA = wrow[tx * 2], bB = wrow[tx * 2 + 1];
            float bv[8] = {bA.x, bA.y, bA.z, bA.w, bB.x, bB.y, bB.z, bB.w};
            #pragma unroll
            for (int e = 0; e < 4; ++e) {
                float a = hs[(e0 + e) * STR + ks + k];
                #pragma unroll
                for (int j = 0; j < 8; ++j) m2[e][j] = fmaf(a, bv[j], m2[e][j]);
            }
        }
        __syncthreads();
    }
    {
        float bb[8];
        #pragma unroll
        for (int j = 0; j < 8; j++) bb[j] = b2[j0 + j];
        #pragma unroll
        for (int e = 0; e < 4; e++)
            #pragma unroll
            for (int j = 0; j < 8; j++) m2[e][j] = silu_f(m2[e][j] + bb[j]);
    }

    // ---- gate: sigmoid(m2 . winf + binf), 16-lane shuffle reduce ----
    {
        float wif[8];
        #pragma unroll
        for (int j = 0; j < 8; j++) wif[j] = winf[j0 + j];
        float bi = binf[0];
        #pragma unroll
        for (int e = 0; e < 4; e++) {
            float p = 0.f;
            #pragma unroll
            for (int j = 0; j < 8; j++) p = fmaf(m2[e][j], wif[j], p);
            #pragma unroll
            for (int off = 8; off >= 1; off >>= 1)
                p += __shfl_down_sync(0xffffffffu, p, off);
            if (tx == 0) s_gd[e0 + e] = 1.f / (1.f + __expf(-(p + bi)));
        }
    }
    __syncthreads();

    // ---- scatter: g_mi[src] += g * m2  (2x red.v4 per thread per edge) ----
    #pragma unroll
    for (int e = 0; e < 4; e++) {
        int st = s_st[e0 + e];
        if (st >= 0) {
            float g = s_gd[e0 + e];
            float* dst = g_mi + (long)st * HID + j0;
            red_add_v4(dst,     g * m2[e][0], g * m2[e][1], g * m2[e][2], g * m2[e][3]);
            red_add_v4(dst + 4, g * m2[e][4], g * m2[e][5], g * m2[e][6], g * m2[e][7]);
        }
    }
}

// ---------------------------------------------------------------------------
// Node kernel: h_new = h + (silu([h|m_i] @ wh1 + bh1) @ wh2 + bh2)
// ---------------------------------------------------------------------------
__global__ void node_kernel(const float* __restrict__ h,
                            const float* __restrict__ wh1, const float* __restrict__ bh1,
                            const float* __restrict__ wh2, const float* __restrict__ bh2,
                            float* __restrict__ out, int N) {
    extern __shared__ float sm[];
    float* ha = sm;              // EB*STR : h rows, later u1
    float* ma = ha + EB * STR;   // EB*STR : m_i rows
    float* ws = ma + EB * STR;   // KC*HID

    const int tid = threadIdx.x;
    const int tx = tid & 15, ty = tid >> 4;
    const int e0 = ty * 4;
    const int j0 = tx * 8;
    const long nbase = (long)blockIdx.x * EB;

    for (int i = tid; i < EB * 32; i += TPB) {
        int row = i >> 5, c4 = i & 31;
        long n = nbase + row;
        float4 v = make_float4(0.f, 0.f, 0.f, 0.f);
        if (n < (long)N) v = ((const float4*)(h + n * HID))[c4];
        ((float4*)(ha + row * STR))[c4] = v;
    }
    for (int i = tid; i < EB * 32; i += TPB) {
        int row = i >> 5, c4 = i & 31;
        long n = nbase + row;
        float4 v = make_float4(0.f, 0.f, 0.f, 0.f);
        if (n < (long)N) v = ((const float4*)(g_mi + n * HID))[c4];
        ((float4*)(ma + row * STR))[c4] = v;
    }
    __syncthreads();

    float acc[4][8];
    #pragma unroll
    for (int e = 0; e < 4; e++)
        #pragma unroll
        for (int j = 0; j < 8; j++) acc[e][j] = 0.f;

    // layer 1: k 0..255 over [h | m_i]
    for (int kb = 0; kb < 8; ++kb) {
        const float4* wsrc = (const float4*)(wh1 + kb * KC * HID);
        for (int i = tid; i < KC * HID / 4; i += TPB) ((float4*)ws)[i] = wsrc[i];
        __syncthreads();
        const float* src = (kb < 4) ? ha : ma;
        const int ks = (kb & 3) * KC;
        #pragma unroll
        for (int k = 0; k < KC; ++k) {
            const float4* wrow = (const float4*)(ws + k * HID);
            float4 bA = wrow[tx * 2], bB = wrow[tx * 2 + 1];
            float bv[8] = {bA.x, bA.y, bA.z, bA.w, bB.x, bB.y, bB.z, bB.w};
            #pragma unroll
            for (int e = 0; e < 4; ++e) {
                float a = src[(e0 + e) * STR + ks + k];
                #pragma unroll
                for (int j = 0; j < 8; ++j) acc[e][j] = fmaf(a, bv[j], acc[e][j]);
            }
        }
        __syncthreads();
    }
    // bias + silu -> u1 into ha
    {
        float bb[8];
        #pragma unroll
        for (int j = 0; j < 8; j++) bb[j] = bh1[j0 + j];
        #pragma unroll
        for (int e = 0; e < 4; e++)
            #pragma unroll
            for (int j = 0; j < 8; j++)
                ha[(e0 + e) * STR + j0 + j] = silu_f(acc[e][j] + bb[j]);
    }

    // layer 2
    float acc2[4][8];
    #pragma unroll
    for (int e = 0; e < 4; e++)
        #pragma unroll
        for (int j = 0; j < 8; j++) acc2[e][j] = 0.f;

    for (int kb = 0; kb < 4; ++kb) {
        const float4* wsrc = (const float4*)(wh2 + kb * KC * HID);
        for (int i = tid; i < KC * HID / 4; i += TPB) ((float4*)ws)[i] = wsrc[i];
        __syncthreads();
        const int ks = kb * KC;
        #pragma unroll
        for (int k = 0; k < KC; ++k) {
            const float4* wrow = (const float4*)(ws + k * HID);
            float4 bA = wrow[tx * 2], bB = wrow[tx * 2 + 1];
            float bv[8] = {bA.x, bA.y, bA.z, bA.w, bB.x, bB.y, bB.z, bB.w};
            #pragma unroll
            for (int e = 0; e < 4; ++e) {
                float a = ha[(e0 + e) * STR + ks + k];
                #pragma unroll
                for (int j = 0; j < 8; ++j) acc2[e][j] = fmaf(a, bv[j], acc2[e][j]);
            }
        }
        __syncthreads();
    }

    // residual + bias, write out
    {
        float bb[8];
        #pragma unroll
        for (int j = 0; j < 8; j++) bb[j] = bh2[j0 + j];
        #pragma unroll
        for (int e = 0; e < 4; e++) {
            long n = nbase + e0 + e;
            if (n < (long)N) {
                const float* hr = h + n * HID + j0;
                float* orow = out + n * HID + j0;
                #pragma unroll
                for (int j = 0; j < 8; j++)
                    orow[j] = hr[j] + acc2[e][j] + bb[j];
            }
        }
    }
}

extern "C" void kernel_launch(void* const* d_in, const int* in_sizes, int n_in,
                              void* d_out, int out_size) {
    const float* h     = (const float*)d_in[0];
    const float* x     = (const float*)d_in[1];
    const int*   edges = (const int*)d_in[2];
    const float* w_e1  = (const float*)d_in[3];
    const float* b_e1  = (const float*)d_in[4];
    const float* w_e2  = (const float*)d_in[5];
    const float* b_e2  = (const float*)d_in[6];
    const float* w_inf = (const float*)d_in[7];
    const float* b_inf = (const float*)d_in[8];
    const float* w_h1  = (const float*)d_in[9];
    const float* b_h1  = (const float*)d_in[10];
    const float* w_h2  = (const float*)d_in[11];
    const float* b_h2  = (const float*)d_in[12];
    float* out = (float*)d_out;

    int N = in_sizes[0] / HID;
    int E = in_sizes[2] / 2;

    const int SMEM_E = (2 * EB * STR + KC * HID + EB) * 4 + 2 * EB * 4;
    const int SMEM_N = (2 * EB * STR + KC * HID) * 4;
    cudaFuncSetAttribute(edge_kernel, cudaFuncAttributeMaxDynamicSharedMemorySize, SMEM_E);
    cudaFuncSetAttribute(node_kernel, cudaFuncAttributeMaxDynamicSharedMemorySize, SMEM_N);

    int n4 = (N * HID) / 4;
    zero_mi_kernel<<<(n4 + TPB - 1) / TPB, TPB>>>(n4);

    edge_kernel<<<(E + EB - 1) / EB, TPB, SMEM_E>>>(
        h, x, edges, w_e1, b_e1, w_e2, b_e2, w_inf, b_inf, N, E);

    node_kernel<<<(N + EB - 1) / EB, TPB, SMEM_N>>>(
        h, w_h1, b_h1, w_h2, b_h2, out, N);
}

// round 3
// speedup vs baseline: 2.2192x; 2.2192x over previous
#include <cuda_runtime.h>
#include <math.h>

#define HID 128
#define EB  64          // edges (or nodes) per block
#define STR 132         // padded smem row stride (floats)
#define KC  32          // K-chunk for weight staging
#define TPB 256

// scratch: m_i segment sum, and per-node precomputed A = h@W1a, B = h@W1b
__device__ float g_mi[6500000];
__device__ float g_A[6500000];
__device__ float g_B[6500000];

__global__ void zero_mi_kernel(int n4) {
    int i = blockIdx.x * blockDim.x + threadIdx.x;
    if (i < n4) ((float4*)g_mi)[i] = make_float4(0.f, 0.f, 0.f, 0.f);
}

__device__ __forceinline__ float silu_f(float v) {
    return v / (1.f + __expf(-v));
}

__device__ __forceinline__ void red_add_v4(float* addr, float a, float b, float c, float d) {
    asm volatile("red.global.add.v4.f32 [%0], {%1, %2, %3, %4};"
                 :: "l"(addr), "f"(a), "f"(b), "f"(c), "f"(d) : "memory");
}

// ---------------------------------------------------------------------------
// Pre kernel: per-node A = h @ W1a, B = h @ W1b
// (W1a = w_e1 rows 0..127, W1b = rows 128..255; no bias here)
// ---------------------------------------------------------------------------
__global__ void pre_kernel(const float* __restrict__ h,
                           const float* __restrict__ w1, int N) {
    extern __shared__ float sm[];
    float* ha = sm;              // EB*STR
    float* ws = ha + EB * STR;   // KC*HID

    const int tid = threadIdx.x;
    const int tx = tid & 15, ty = tid >> 4;
    const int e0 = ty * 4;
    const int j0 = tx * 8;
    const long nbase = (long)blockIdx.x * EB;

    for (int i = tid; i < EB * 32; i += TPB) {
        int row = i >> 5, c4 = i & 31;
        long n = nbase + row;
        float4 v = make_float4(0.f, 0.f, 0.f, 0.f);
        if (n < (long)N) v = ((const float4*)(h + n * HID))[c4];
        ((float4*)(ha + row * STR))[c4] = v;
    }
    __syncthreads();

    #pragma unroll
    for (int half = 0; half < 2; ++half) {
        float acc[4][8];
        #pragma unroll
        for (int e = 0; e < 4; e++)
            #pragma unroll
            for (int j = 0; j < 8; j++) acc[e][j] = 0.f;

        const float* wbase = w1 + (long)half * HID * HID;
        for (int kb = 0; kb < 4; ++kb) {
            const float4* wsrc = (const float4*)(wbase + kb * KC * HID);
            for (int i = tid; i < KC * HID / 4; i += TPB) ((float4*)ws)[i] = wsrc[i];
            __syncthreads();
            const int ks = kb * KC;
            #pragma unroll
            for (int k = 0; k < KC; ++k) {
                const float4* wrow = (const float4*)(ws + k * HID);
                float4 bA = wrow[tx * 2], bB = wrow[tx * 2 + 1];
                float bv[8] = {bA.x, bA.y, bA.z, bA.w, bB.x, bB.y, bB.z, bB.w};
                #pragma unroll
                for (int e = 0; e < 4; ++e) {
                    float a = ha[(e0 + e) * STR + ks + k];
                    #pragma unroll
                    for (int j = 0; j < 8; ++j) acc[e][j] = fmaf(a, bv[j], acc[e][j]);
                }
            }
            __syncthreads();
        }

        float* dst = half == 0 ? g_A : g_B;
        #pragma unroll
        for (int e = 0; e < 4; e++) {
            long n = nbase + e0 + e;
            if (n < (long)N) {
                float* orow = dst + n * HID + j0;
                #pragma unroll
                for (int j = 0; j < 8; j++) orow[j] = acc[e][j];
            }
        }
    }
}

// ---------------------------------------------------------------------------
// Edge kernel: m1 = silu(A[s] + B[t] + d*w1d + b1)   (gather-add, no GEMM)
//              m2 = silu(m1 @ w2 + b2)
//              g  = sigmoid(m2 . winf + binf)
//              g_mi[s] += g * m2
// ---------------------------------------------------------------------------
__global__ void edge_kernel(const float* __restrict__ x,
                            const int* __restrict__ edges,
                            const float* __restrict__ w1, const float* __restrict__ b1,
                            const float* __restrict__ w2, const float* __restrict__ b2,
                            const float* __restrict__ winf, const float* __restrict__ binf,
                            int N, int E) {
    extern __shared__ float sm[];
    float* hs   = sm;                  // EB*STR  : A[s]+B[t], then m1
    float* ws   = hs + EB * STR;       // KC*HID  : weight tile
    float* s_gd = ws + KC * HID;       // EB      : dist, later gate
    int*   s_st = (int*)(s_gd + EB);   // EB
    int*   s_en = s_st + EB;           // EB

    const int tid = threadIdx.x;
    const int tx = tid & 15, ty = tid >> 4;
    const int e0 = ty * 4;
    const int j0 = tx * 8;
    const long ebase = (long)blockIdx.x * EB;

    if (tid < EB) {
        long e = ebase + tid;
        int st = -1, en = -1; float d = 0.f;
        if (e < (long)E) {
            st = edges[2 * e];
            en = edges[2 * e + 1];
            float dx = x[3 * st + 0] - x[3 * en + 0];
            float dy = x[3 * st + 1] - x[3 * en + 1];
            float dz = x[3 * st + 2] - x[3 * en + 2];
            d = sqrtf(dx * dx + dy * dy + dz * dz);
        }
        s_st[tid] = st; s_en[tid] = en; s_gd[tid] = d;
    }
    __syncthreads();

    // gather A[src] + B[dst] (float4, L2-resident)
    for (int i = tid; i < EB * 32; i += TPB) {
        int row = i >> 5, c4 = i & 31;
        int rs = s_st[row], rt = s_en[row];
        float4 v = make_float4(0.f, 0.f, 0.f, 0.f);
        if (rs >= 0) {
            float4 a = ((const float4*)(g_A + (long)rs * HID))[c4];
            float4 b = ((const float4*)(g_B + (long)rt * HID))[c4];
            v = make_float4(a.x + b.x, a.y + b.y, a.z + b.z, a.w + b.w);
        }
        ((float4*)(hs + row * STR))[c4] = v;
    }
    __syncthreads();

    // m1 = silu(hs + d*w1d + b1) in place (each thread owns its cells)
    {
        float wr[8], bb[8];
        #pragma unroll
        for (int j = 0; j < 8; j++) { wr[j] = w1[256 * HID + j0 + j]; bb[j] = b1[j0 + j]; }
        #pragma unroll
        for (int e = 0; e < 4; e++) {
            float d = s_gd[e0 + e];
            #pragma unroll
            for (int j = 0; j < 8; j++) {
                float v = fmaf(d, wr[j], hs[(e0 + e) * STR + j0 + j]) + bb[j];
                hs[(e0 + e) * STR + j0 + j] = silu_f(v);
            }
        }
    }

    // ---- layer 2: m2 = silu(m1 @ w2 + b2) ----
    float m2[4][8];
    #pragma unroll
    for (int e = 0; e < 4; e++)
        #pragma unroll
        for (int j = 0; j < 8; j++) m2[e][j] = 0.f;

    for (int kb = 0; kb < 4; ++kb) {
        const float4* wsrc = (const float4*)(w2 + kb * KC * HID);
        for (int i = tid; i < KC * HID / 4; i += TPB) ((float4*)ws)[i] = wsrc[i];
        __syncthreads();   // also orders m1 writes before cross-thread reads
        const int ks = kb * KC;
        #pragma unroll
        for (int k = 0; k < KC; ++k) {
            const float4* wrow = (const float4*)(ws + k * HID);
            float4 bA = wrow[tx * 2], bB = wrow[tx * 2 + 1];
            float bv[8] = {bA.x, bA.y, bA.z, bA.w, bB.x, bB.y, bB.z, bB.w};
            #pragma unroll
            for (int e = 0; e < 4; ++e) {
                float a = hs[(e0 + e) * STR + ks + k];
                #pragma unroll
                for (int j = 0; j < 8; ++j) m2[e][j] = fmaf(a, bv[j], m2[e][j]);
            }
        }
        __syncthreads();
    }
    {
        float bb[8];
        #pragma unroll
        for (int j = 0; j < 8; j++) bb[j] = b2[j0 + j];
        #pragma unroll
        for (int e = 0; e < 4; e++)
            #pragma unroll
            for (int j = 0; j < 8; j++) m2[e][j] = silu_f(m2[e][j] + bb[j]);
    }

    // ---- gate: sigmoid(m2 . winf + binf), 16-lane shuffle reduce ----
    {
        float wif[8];
        #pragma unroll
        for (int j = 0; j < 8; j++) wif[j] = winf[j0 + j];
        float bi = binf[0];
        #pragma unroll
        for (int e = 0; e < 4; e++) {
            float p = 0.f;
            #pragma unroll
            for (int j = 0; j < 8; j++) p = fmaf(m2[e][j], wif[j], p);
            #pragma unroll
            for (int off = 8; off >= 1; off >>= 1)
                p += __shfl_down_sync(0xffffffffu, p, off);
            if (tx == 0) s_gd[e0 + e] = 1.f / (1.f + __expf(-(p + bi)));
        }
    }
    __syncthreads();

    // ---- scatter: g_mi[src] += g * m2 ----
    #pragma unroll
    for (int e = 0; e < 4; e++) {
        int st = s_st[e0 + e];
        if (st >= 0) {
            float g = s_gd[e0 + e];
            float* dst = g_mi + (long)st * HID + j0;
            red_add_v4(dst,     g * m2[e][0], g * m2[e][1], g * m2[e][2], g * m2[e][3]);
            red_add_v4(dst + 4, g * m2[e][4], g * m2[e][5], g * m2[e][6], g * m2[e][7]);
        }
    }
}

// ---------------------------------------------------------------------------
// Node kernel: h_new = h + (silu([h|m_i] @ wh1 + bh1) @ wh2 + bh2)
// ---------------------------------------------------------------------------
__global__ void node_kernel(const float* __restrict__ h,
                            const float* __restrict__ wh1, const float* __restrict__ bh1,
                            const float* __restrict__ wh2, const float* __restrict__ bh2,
                            float* __restrict__ out, int N) {
    extern __shared__ float sm[];
    float* ha = sm;              // EB*STR : h rows, later u1
    float* ma = ha + EB * STR;   // EB*STR : m_i rows
    float* ws = ma + EB * STR;   // KC*HID

    const int tid = threadIdx.x;
    const int tx = tid & 15, ty = tid >> 4;
    const int e0 = ty * 4;
    const int j0 = tx * 8;
    const long nbase = (long)blockIdx.x * EB;

    for (int i = tid; i < EB * 32; i += TPB) {
        int row = i >> 5, c4 = i & 31;
        long n = nbase + row;
        float4 v = make_float4(0.f, 0.f, 0.f, 0.f);
        if (n < (long)N) v = ((const float4*)(h + n * HID))[c4];
        ((float4*)(ha + row * STR))[c4] = v;
    }
    for (int i = tid; i < EB * 32; i += TPB) {
        int row = i >> 5, c4 = i & 31;
        long n = nbase + row;
        float4 v = make_float4(0.f, 0.f, 0.f, 0.f);
        if (n < (long)N) v = ((const float4*)(g_mi + n * HID))[c4];
        ((float4*)(ma + row * STR))[c4] = v;
    }
    __syncthreads();

    float acc[4][8];
    #pragma unroll
    for (int e = 0; e < 4; e++)
        #pragma unroll
        for (int j = 0; j < 8; j++) acc[e][j] = 0.f;

    // layer 1: k 0..255 over [h | m_i]
    for (int kb = 0; kb < 8; ++kb) {
        const float4* wsrc = (const float4*)(wh1 + kb * KC * HID);
        for (int i = tid; i < KC * HID / 4; i += TPB) ((float4*)ws)[i] = wsrc[i];
        __syncthreads();
        const float* src = (kb < 4) ? ha : ma;
        const int ks = (kb & 3) * KC;
        #pragma unroll
        for (int k = 0; k < KC; ++k) {
            const float4* wrow = (const float4*)(ws + k * HID);
            float4 bA = wrow[tx * 2], bB = wrow[tx * 2 + 1];
            float bv[8] = {bA.x, bA.y, bA.z, bA.w, bB.x, bB.y, bB.z, bB.w};
            #pragma unroll
            for (int e = 0; e < 4; ++e) {
                float a = src[(e0 + e) * STR + ks + k];
                #pragma unroll
                for (int j = 0; j < 8; ++j) acc[e][j] = fmaf(a, bv[j], acc[e][j]);
            }
        }
        __syncthreads();
    }
    // bias + silu -> u1 into ha
    {
        float bb[8];
        #pragma unroll
        for (int j = 0; j < 8; j++) bb[j] = bh1[j0 + j];
        #pragma unroll
        for (int e = 0; e < 4; e++)
            #pragma unroll
            for (int j = 0; j < 8; j++)
                ha[(e0 + e) * STR + j0 + j] = silu_f(acc[e][j] + bb[j]);
    }

    // layer 2
    float acc2[4][8];
    #pragma unroll
    for (int e = 0; e < 4; e++)
        #pragma unroll
        for (int j = 0; j < 8; j++) acc2[e][j] = 0.f;

    for (int kb = 0; kb < 4; ++kb) {
        const float4* wsrc = (const float4*)(wh2 + kb * KC * HID);
        for (int i = tid; i < KC * HID / 4; i += TPB) ((float4*)ws)[i] = wsrc[i];
        __syncthreads();
        const int ks = kb * KC;
        #pragma unroll
        for (int k = 0; k < KC; ++k) {
            const float4* wrow = (const float4*)(ws + k * HID);
            float4 bA = wrow[tx * 2], bB = wrow[tx * 2 + 1];
            float bv[8] = {bA.x, bA.y, bA.z, bA.w, bB.x, bB.y, bB.z, bB.w};
            #pragma unroll
            for (int e = 0; e < 4; ++e) {
                float a = ha[(e0 + e) * STR + ks + k];
                #pragma unroll
                for (int j = 0; j < 8; ++j) acc2[e][j] = fmaf(a, bv[j], acc2[e][j]);
            }
        }
        __syncthreads();
    }

    // residual + bias, write out
    {
        float bb[8];
        #pragma unroll
        for (int j = 0; j < 8; j++) bb[j] = bh2[j0 + j];
        #pragma unroll
        for (int e = 0; e < 4; e++) {
            long n = nbase + e0 + e;
            if (n < (long)N) {
                const float* hr = h + n * HID + j0;
                float* orow = out + n * HID + j0;
                #pragma unroll
                for (int j = 0; j < 8; j++)
                    orow[j] = hr[j] + acc2[e][j] + bb[j];
            }
        }
    }
}

extern "C" void kernel_launch(void* const* d_in, const int* in_sizes, int n_in,
                              void* d_out, int out_size) {
    const float* h     = (const float*)d_in[0];
    const float* x     = (const float*)d_in[1];
    const int*   edges = (const int*)d_in[2];
    const float* w_e1  = (const float*)d_in[3];
    const float* b_e1  = (const float*)d_in[4];
    const float* w_e2  = (const float*)d_in[5];
    const float* b_e2  = (const float*)d_in[6];
    const float* w_inf = (const float*)d_in[7];
    const float* b_inf = (const float*)d_in[8];
    const float* w_h1  = (const float*)d_in[9];
    const float* b_h1  = (const float*)d_in[10];
    const float* w_h2  = (const float*)d_in[11];
    const float* b_h2  = (const float*)d_in[12];
    float* out = (float*)d_out;

    int N = in_sizes[0] / HID;
    int E = in_sizes[2] / 2;

    const int SMEM_P = (EB * STR + KC * HID) * 4;
    const int SMEM_E = (EB * STR + KC * HID + EB) * 4 + 2 * EB * 4;
    const int SMEM_N = (2 * EB * STR + KC * HID) * 4;
    cudaFuncSetAttribute(pre_kernel,  cudaFuncAttributeMaxDynamicSharedMemorySize, SMEM_P);
    cudaFuncSetAttribute(edge_kernel, cudaFuncAttributeMaxDynamicSharedMemorySize, SMEM_E);
    cudaFuncSetAttribute(node_kernel, cudaFuncAttributeMaxDynamicSharedMemorySize, SMEM_N);

    int n4 = (N * HID) / 4;
    zero_mi_kernel<<<(n4 + TPB - 1) / TPB, TPB>>>(n4);

    pre_kernel<<<(N + EB - 1) / EB, TPB, SMEM_P>>>(h, w_e1, N);

    edge_kernel<<<(E + EB - 1) / EB, TPB, SMEM_E>>>(
        x, edges, w_e1, b_e1, w_e2, b_e2, w_inf, b_inf, N, E);

    node_kernel<<<(N + EB - 1) / EB, TPB, SMEM_N>>>(
        h, w_h1, b_h1, w_h2, b_h2, out, N);
}

// round 5
// speedup vs baseline: 2.5557x; 1.1516x over previous
#include <cuda_runtime.h>
#include <math.h>

#define HID 128
#define EB  64          // rows (edges/nodes) per block
#define STR 132         // padded smem row stride (floats)
#define KC  32          // K-chunk for weight staging
#define TPB 128         // threads per block: 16 col-groups x 8 row-groups
#define TM  8           // rows per thread
#define TN  8           // cols per thread

// scratch: m_i segment sum, and per-node precomputed A = h@W1a, B = h@W1b
__device__ float g_mi[6500000];
__device__ float g_A[6500000];
__device__ float g_B[6500000];

__global__ void zero_mi_kernel(int n4) {
    int i = blockIdx.x * blockDim.x + threadIdx.x;
    if (i < n4) ((float4*)g_mi)[i] = make_float4(0.f, 0.f, 0.f, 0.f);
}

__device__ __forceinline__ float silu_f(float v) {
    return v / (1.f + __expf(-v));
}

__device__ __forceinline__ void red_add_v4(float* addr, float a, float b, float c, float d) {
    asm volatile("red.global.add.v4.f32 [%0], {%1, %2, %3, %4};"
                 :: "l"(addr), "f"(a), "f"(b), "f"(c), "f"(d) : "memory");
}

// ---------------------------------------------------------------------------
// Pre kernel: per-node A = h @ W1a, B = h @ W1b (w_e1 rows 0..127 / 128..255)
// ---------------------------------------------------------------------------
__global__ void __launch_bounds__(TPB, 4)
pre_kernel(const float* __restrict__ h, const float* __restrict__ w1, int N) {
    extern __shared__ float sm[];
    float* ha = sm;              // EB*STR
    float* ws = ha + EB * STR;   // KC*HID

    const int tid = threadIdx.x;
    const int tx = tid & 15, ty = tid >> 4;
    const int e0 = ty * TM;
    const int j0 = tx * TN;
    const long nbase = (long)blockIdx.x * EB;

    for (int i = tid; i < EB * 32; i += TPB) {
        int row = i >> 5, c4 = i & 31;
        long n = nbase + row;
        float4 v = make_float4(0.f, 0.f, 0.f, 0.f);
        if (n < (long)N) v = ((const float4*)(h + n * HID))[c4];
        ((float4*)(ha + row * STR))[c4] = v;
    }
    __syncthreads();

    for (int half = 0; half < 2; ++half) {
        float acc[TM][TN];
        #pragma unroll
        for (int e = 0; e < TM; e++)
            #pragma unroll
            for (int j = 0; j < TN; j++) acc[e][j] = 0.f;

        const float* wbase = w1 + (long)half * HID * HID;
        for (int kb = 0; kb < 4; ++kb) {
            const float4* wsrc = (const float4*)(wbase + kb * KC * HID);
            for (int i = tid; i < KC * HID / 4; i += TPB) ((float4*)ws)[i] = wsrc[i];
            __syncthreads();
            const int ks = kb * KC;
            #pragma unroll
            for (int k = 0; k < KC; ++k) {
                const float4* wrow = (const float4*)(ws + k * HID);
                float4 bA = wrow[tx * 2], bB = wrow[tx * 2 + 1];
                float bv[TN] = {bA.x, bA.y, bA.z, bA.w, bB.x, bB.y, bB.z, bB.w};
                float av[TM];
                #pragma unroll
                for (int e = 0; e < TM; ++e) av[e] = ha[(e0 + e) * STR + ks + k];
                #pragma unroll
                for (int e = 0; e < TM; ++e)
                    #pragma unroll
                    for (int j = 0; j < TN; ++j) acc[e][j] = fmaf(av[e], bv[j], acc[e][j]);
            }
            __syncthreads();
        }

        float* dst = half == 0 ? g_A : g_B;
        #pragma unroll
        for (int e = 0; e < TM; e++) {
            long n = nbase + e0 + e;
            if (n < (long)N) {
                float* orow = dst + n * HID + j0;
                #pragma unroll
                for (int j = 0; j < TN; j++) orow[j] = acc[e][j];
            }
        }
    }
}

// ---------------------------------------------------------------------------
// Edge kernel: m1 = silu(A[s] + B[t] + d*w1d + b1)   (gather-add)
//              m2 = silu(m1 @ w2 + b2)
//              g  = sigmoid(m2 . winf + binf)
//              g_mi[s] += g * m2
// ---------------------------------------------------------------------------
__global__ void __launch_bounds__(TPB, 4)
edge_kernel(const float* __restrict__ x, const int* __restrict__ edges,
            const float* __restrict__ w1, const float* __restrict__ b1,
            const float* __restrict__ w2, const float* __restrict__ b2,
            const float* __restrict__ winf, const float* __restrict__ binf,
            int N, int E) {
    extern __shared__ float sm[];
    float* hs   = sm;                  // EB*STR  : A[s]+B[t], then m1
    float* ws   = hs + EB * STR;       // KC*HID
    float* s_gd = ws + KC * HID;       // EB : dist, later gate
    int*   s_st = (int*)(s_gd + EB);   // EB
    int*   s_en = s_st + EB;           // EB

    const int tid = threadIdx.x;
    const int tx = tid & 15, ty = tid >> 4;
    const int e0 = ty * TM;
    const int j0 = tx * TN;
    const long ebase = (long)blockIdx.x * EB;

    if (tid < EB) {
        long e = ebase + tid;
        int st = -1, en = -1; float d = 0.f;
        if (e < (long)E) {
            st = edges[2 * e];
            en = edges[2 * e + 1];
            float dx = x[3 * st + 0] - x[3 * en + 0];
            float dy = x[3 * st + 1] - x[3 * en + 1];
            float dz = x[3 * st + 2] - x[3 * en + 2];
            d = sqrtf(dx * dx + dy * dy + dz * dz);
        }
        s_st[tid] = st; s_en[tid] = en; s_gd[tid] = d;
    }
    __syncthreads();

    // gather A[src] + B[dst] (float4, L2-resident)
    for (int i = tid; i < EB * 32; i += TPB) {
        int row = i >> 5, c4 = i & 31;
        int rs = s_st[row], rt = s_en[row];
        float4 v = make_float4(0.f, 0.f, 0.f, 0.f);
        if (rs >= 0) {
            float4 a = ((const float4*)(g_A + (long)rs * HID))[c4];
            float4 b = ((const float4*)(g_B + (long)rt * HID))[c4];
            v = make_float4(a.x + b.x, a.y + b.y, a.z + b.z, a.w + b.w);
        }
        ((float4*)(hs + row * STR))[c4] = v;
    }
    __syncthreads();

    // m1 = silu(hs + d*w1d + b1) in place (each thread owns its 8x8 cells)
    {
        float wr[TN], bb[TN];
        #pragma unroll
        for (int j = 0; j < TN; j++) { wr[j] = w1[256 * HID + j0 + j]; bb[j] = b1[j0 + j]; }
        #pragma unroll
        for (int e = 0; e < TM; e++) {
            float d = s_gd[e0 + e];
            #pragma unroll
            for (int j = 0; j < TN; j++) {
                float v = fmaf(d, wr[j], hs[(e0 + e) * STR + j0 + j]) + bb[j];
                hs[(e0 + e) * STR + j0 + j] = silu_f(v);
            }
        }
    }

    // ---- layer 2: m2 = silu(m1 @ w2 + b2) ----
    float m2[TM][TN];
    #pragma unroll
    for (int e = 0; e < TM; e++)
        #pragma unroll
        for (int j = 0; j < TN; j++) m2[e][j] = 0.f;

    for (int kb = 0; kb < 4; ++kb) {
        const float4* wsrc = (const float4*)(w2 + kb * KC * HID);
        for (int i = tid; i < KC * HID / 4; i += TPB) ((float4*)ws)[i] = wsrc[i];
        __syncthreads();   // also orders m1 writes before cross-thread reads
        const int ks = kb * KC;
        #pragma unroll
        for (int k = 0; k < KC; ++k) {
            const float4* wrow = (const float4*)(ws + k * HID);
            float4 bA = wrow[tx * 2], bB = wrow[tx * 2 + 1];
            float bv[TN] = {bA.x, bA.y, bA.z, bA.w, bB.x, bB.y, bB.z, bB.w};
            float av[TM];
            #pragma unroll
            for (int e = 0; e < TM; ++e) av[e] = hs[(e0 + e) * STR + ks + k];
            #pragma unroll
            for (int e = 0; e < TM; ++e)
                #pragma unroll
                for (int j = 0; j < TN; ++j) m2[e][j] = fmaf(av[e], bv[j], m2[e][j]);
        }
        __syncthreads();
    }
    {
        float bb[TN];
        #pragma unroll
        for (int j = 0; j < TN; j++) bb[j] = b2[j0 + j];
        #pragma unroll
        for (int e = 0; e < TM; e++)
            #pragma unroll
            for (int j = 0; j < TN; j++) m2[e][j] = silu_f(m2[e][j] + bb[j]);
    }

    // ---- gate: sigmoid(m2 . winf + binf), 16-lane shuffle reduce ----
    {
        float wif[TN];
        #pragma unroll
        for (int j = 0; j < TN; j++) wif[j] = winf[j0 + j];
        float bi = binf[0];
        #pragma unroll
        for (int e = 0; e < TM; e++) {
            float p = 0.f;
            #pragma unroll
            for (int j = 0; j < TN; j++) p = fmaf(m2[e][j], wif[j], p);
            #pragma unroll
            for (int off = 8; off >= 1; off >>= 1)
                p += __shfl_down_sync(0xffffffffu, p, off);
            if (tx == 0) s_gd[e0 + e] = 1.f / (1.f + __expf(-(p + bi)));
        }
    }
    __syncthreads();

    // ---- scatter: g_mi[src] += g * m2 ----
    #pragma unroll
    for (int e = 0; e < TM; e++) {
        int st = s_st[e0 + e];
        if (st >= 0) {
            float g = s_gd[e0 + e];
            float* dst = g_mi + (long)st * HID + j0;
            red_add_v4(dst,     g * m2[e][0], g * m2[e][1], g * m2[e][2], g * m2[e][3]);
            red_add_v4(dst + 4, g * m2[e][4], g * m2[e][5], g * m2[e][6], g * m2[e][7]);
        }
    }
}

// ---------------------------------------------------------------------------
// Node kernel: h_new = h + (silu([h|m_i] @ wh1 + bh1) @ wh2 + bh2)
// ---------------------------------------------------------------------------
__global__ void __launch_bounds__(TPB, 4)
node_kernel(const float* __restrict__ h,
            const float* __restrict__ wh1, const float* __restrict__ bh1,
            const float* __restrict__ wh2, const float* __restrict__ bh2,
            float* __restrict__ out, int N) {
    extern __shared__ float sm[];
    float* ha = sm;              // EB*STR : h rows, later u1
    float* ma = ha + EB * STR;   // EB*STR : m_i rows
    float* ws = ma + EB * STR;   // KC*HID

    const int tid = threadIdx.x;
    const int tx = tid & 15, ty = tid >> 4;
    const int e0 = ty * TM;
    const int j0 = tx * TN;
    const long nbase = (long)blockIdx.x * EB;

    for (int i = tid; i < EB * 32; i += TPB) {
        int row = i >> 5, c4 = i & 31;
        long n = nbase + row;
        float4 v = make_float4(0.f, 0.f, 0.f, 0.f);
        if (n < (long)N) v = ((const float4*)(h + n * HID))[c4];
        ((float4*)(ha + row * STR))[c4] = v;
    }
    for (int i = tid; i < EB * 32; i += TPB) {
        int row = i >> 5, c4 = i & 31;
        long n = nbase + row;
        float4 v = make_float4(0.f, 0.f, 0.f, 0.f);
        if (n < (long)N) v = ((const float4*)(g_mi + n * HID))[c4];
        ((float4*)(ma + row * STR))[c4] = v;
    }
    __syncthreads();

    float acc[TM][TN];
    #pragma unroll
    for (int e = 0; e < TM; e++)
        #pragma unroll
        for (int j = 0; j < TN; j++) acc[e][j] = 0.f;

    // layer 1: k 0..255 over [h | m_i]
    for (int kb = 0; kb < 8; ++kb) {
        const float4* wsrc = (const float4*)(wh1 + kb * KC * HID);
        for (int i = tid; i < KC * HID / 4; i += TPB) ((float4*)ws)[i] = wsrc[i];
        __syncthreads();
        const float* src = (kb < 4) ? ha : ma;
        const int ks = (kb & 3) * KC;
        #pragma unroll
        for (int k = 0; k < KC; ++k) {
            const float4* wrow = (const float4*)(ws + k * HID);
            float4 bA = wrow[tx * 2], bB = wrow[tx * 2 + 1];
            float bv[TN] = {bA.x, bA.y, bA.z, bA.w, bB.x, bB.y, bB.z, bB.w};
            float av[TM];
            #pragma unroll
            for (int e = 0; e < TM; ++e) av[e] = src[(e0 + e) * STR + ks + k];
            #pragma unroll
            for (int e = 0; e < TM; ++e)
                #pragma unroll
                for (int j = 0; j < TN; ++j) acc[e][j] = fmaf(av[e], bv[j], acc[e][j]);
        }
        __syncthreads();
    }
    // bias + silu -> u1 into ha
    {
        float bb[TN];
        #pragma unroll
        for (int j = 0; j < TN; j++) bb[j] = bh1[j0 + j];
        #pragma unroll
        for (int e = 0; e < TM; e++)
            #pragma unroll
            for (int j = 0; j < TN; j++)
                ha[(e0 + e) * STR + j0 + j] = silu_f(acc[e][j] + bb[j]);
    }

    // layer 2
    float acc2[TM][TN];
    #pragma unroll
    for (int e = 0; e < TM; e++)
        #pragma unroll
        for (int j = 0; j < TN; j++) acc2[e][j] = 0.f;

    for (int kb = 0; kb < 4; ++kb) {
        const float4* wsrc = (const float4*)(wh2 + kb * KC * HID);
        for (int i = tid; i < KC * HID / 4; i += TPB) ((float4*)ws)[i] = wsrc[i];
        __syncthreads();   // orders u1 writes before cross-thread reads
        const int ks = kb * KC;
        #pragma unroll
        for (int k = 0; k < KC; ++k) {
            const float4* wrow = (const float4*)(ws + k * HID);
            float4 bA = wrow[tx * 2], bB = wrow[tx * 2 + 1];
            float bv[TN] = {bA.x, bA.y, bA.z, bA.w, bB.x, bB.y, bB.z, bB.w};
            float av[TM];
            #pragma unroll
            for (int e = 0; e < TM; ++e) av[e] = ha[(e0 + e) * STR + ks + k];
            #pragma unroll
            for (int e = 0; e < TM; ++e)
                #pragma unroll
                for (int j = 0; j < TN; ++j) acc2[e][j] = fmaf(av[e], bv[j], acc2[e][j]);
        }
        __syncthreads();
    }

    // residual + bias, write out
    {
        float bb[TN];
        #pragma unroll
        for (int j = 0; j < TN; j++) bb[j] = bh2[j0 + j];
        #pragma unroll
        for (int e = 0; e < TM; e++) {
            long n = nbase + e0 + e;
            if (n < (long)N) {
                const float* hr = h + n * HID + j0;
                float* orow = out + n * HID + j0;
                #pragma unroll
                for (int j = 0; j < TN; j++)
                    orow[j] = hr[j] + acc2[e][j] + bb[j];
            }
        }
    }
}

extern "C" void kernel_launch(void* const* d_in, const int* in_sizes, int n_in,
                              void* d_out, int out_size) {
    const float* h     = (const float*)d_in[0];
    const float* x     = (const float*)d_in[1];
    const int*   edges = (const int*)d_in[2];
    const float* w_e1  = (const float*)d_in[3];
    const float* b_e1  = (const float*)d_in[4];
    const float* w_e2  = (const float*)d_in[5];
    const float* b_e2  = (const float*)d_in[6];
    const float* w_inf = (const float*)d_in[7];
    const float* b_inf = (const float*)d_in[8];
    const float* w_h1  = (const float*)d_in[9];
    const float* b_h1  = (const float*)d_in[10];
    const float* w_h2  = (const float*)d_in[11];
    const float* b_h2  = (const float*)d_in[12];
    float* out = (float*)d_out;

    int N = in_sizes[0] / HID;
    int E = in_sizes[2] / 2;

    const int SMEM_P = (EB * STR + KC * HID) * 4;
    const int SMEM_E = (EB * STR + KC * HID + EB) * 4 + 2 * EB * 4;
    const int SMEM_N = (2 * EB * STR + KC * HID) * 4;
    cudaFuncSetAttribute(pre_kernel,  cudaFuncAttributeMaxDynamicSharedMemorySize, SMEM_P);
    cudaFuncSetAttribute(edge_kernel, cudaFuncAttributeMaxDynamicSharedMemorySize, SMEM_E);
    cudaFuncSetAttribute(node_kernel, cudaFuncAttributeMaxDynamicSharedMemorySize, SMEM_N);

    int n4 = (N * HID) / 4;
    zero_mi_kernel<<<(n4 + 255) / 256, 256>>>(n4);

    pre_kernel<<<(N + EB - 1) / EB, TPB, SMEM_P>>>(h, w_e1, N);

    edge_kernel<<<(E + EB - 1) / EB, TPB, SMEM_E>>>(
        x, edges, w_e1, b_e1, w_e2, b_e2, w_inf, b_inf, N, E);

    node_kernel<<<(N + EB - 1) / EB, TPB, SMEM_N>>>(
        h, w_h1, b_h1, w_h2, b_h2, out, N);
}

// round 6
// speedup vs baseline: 3.7308x; 1.4598x over previous
#include <cuda_runtime.h>
#include <math.h>
#include <stdint.h>

#define HID 128
#define EB  64          // rows (edges/nodes) per block
#define STR 132         // padded smem row stride (floats) -> conflict-free A frags
#define KC  32          // K-chunk for weight staging
#define TPB 128         // 4 warps; each warp owns a 16-row band

// scratch: m_i segment sum, per-node A = h@W1a, B = h@W1b
__device__ float g_mi[6500000];
__device__ float g_A[6500000];
__device__ float g_B[6500000];

__global__ void zero_mi_kernel(int n4) {
    int i = blockIdx.x * blockDim.x + threadIdx.x;
    if (i < n4) ((float4*)g_mi)[i] = make_float4(0.f, 0.f, 0.f, 0.f);
}

__device__ __forceinline__ float silu_f(float v) {
    return v / (1.f + __expf(-v));
}

__device__ __forceinline__ void red_add_v4(float* addr, float a, float b, float c, float d) {
    asm volatile("red.global.add.v4.f32 [%0], {%1, %2, %3, %4};"
                 :: "l"(addr), "f"(a), "f"(b), "f"(c), "f"(d) : "memory");
}

__device__ __forceinline__ uint32_t f2tf(float v) {
    uint32_t t;
    asm("cvt.rna.tf32.f32 %0, %1;" : "=r"(t) : "f"(v));
    return t;
}

__device__ __forceinline__ void mma_tf32(float* c,
                                         uint32_t a0, uint32_t a1, uint32_t a2, uint32_t a3,
                                         uint32_t b0, uint32_t b1) {
    asm volatile("mma.sync.aligned.m16n8k8.row.col.f32.tf32.tf32.f32 "
                 "{%0,%1,%2,%3}, {%4,%5,%6,%7}, {%8,%9}, {%0,%1,%2,%3};"
                 : "+f"(c[0]), "+f"(c[1]), "+f"(c[2]), "+f"(c[3])
                 : "r"(a0), "r"(a1), "r"(a2), "r"(a3), "r"(b0), "r"(b1));
}

// stage a KC x HID fp32 weight chunk into smem as tf32, XOR-swizzled so that
// B-fragment loads are bank-conflict-free.
__device__ __forceinline__ void stage_w(uint32_t* ws, const float* __restrict__ wsrc, int tid) {
    for (int i = tid; i < KC * HID; i += TPB) {
        int r = i >> 7, c = i & 127;
        ws[(r << 7) + (c ^ ((r & 3) << 3))] = f2tf(wsrc[i]);
    }
}

// warp computes acc[16 n-tiles][4] += Act[rowbase..rowbase+16, kcol0..kcol0+KC) @ Wchunk
__device__ __forceinline__ void warp_mma_chunk(const float* __restrict__ act, int rowbase,
                                               int kcol0, const uint32_t* __restrict__ ws,
                                               float acc[16][4], int lane) {
    const int m = lane & 3, q = lane >> 2;
    #pragma unroll
    for (int kk = 0; kk < KC; kk += 8) {
        const float* ar0 = act + (rowbase + q) * STR + kcol0 + kk + m;
        uint32_t a0 = f2tf(ar0[0]);
        uint32_t a1 = f2tf(ar0[8 * STR]);
        uint32_t a2 = f2tf(ar0[4]);
        uint32_t a3 = f2tf(ar0[8 * STR + 4]);
        const uint32_t* w0 = ws + (kk + m) * HID;
        const int sw = m << 3;
        #pragma unroll
        for (int j = 0; j < 16; ++j) {
            uint32_t b0 = w0[(j * 8 + q) ^ sw];
            uint32_t b1 = w0[4 * HID + ((j * 8 + q) ^ sw)];
            mma_tf32(acc[j], a0, a1, a2, a3, b0, b1);
        }
    }
}

// ---------------------------------------------------------------------------
// Pre kernel: per-node A = h @ W1a, B = h @ W1b (w_e1 rows 0..127 / 128..255)
// ---------------------------------------------------------------------------
__global__ void __launch_bounds__(TPB, 4)
pre_kernel(const float* __restrict__ h, const float* __restrict__ w1, int N) {
    extern __shared__ float sm[];
    float* ha = sm;                                // EB*STR
    uint32_t* ws = (uint32_t*)(ha + EB * STR);     // KC*HID

    const int tid = threadIdx.x;
    const int lane = tid & 31, warp = tid >> 5;
    const int rowbase = warp * 16;
    const int m = lane & 3, q = lane >> 2;
    const long nbase = (long)blockIdx.x * EB;

    for (int i = tid; i < EB * 32; i += TPB) {
        int row = i >> 5, c4 = i & 31;
        long n = nbase + row;
        float4 v = make_float4(0.f, 0.f, 0.f, 0.f);
        if (n < (long)N) v = ((const float4*)(h + n * HID))[c4];
        ((float4*)(ha + row * STR))[c4] = v;
    }
    __syncthreads();

    for (int half = 0; half < 2; ++half) {
        float acc[16][4];
        #pragma unroll
        for (int j = 0; j < 16; ++j)
            #pragma unroll
            for (int t = 0; t < 4; ++t) acc[j][t] = 0.f;

        const float* wbase = w1 + (long)half * HID * HID;
        for (int kb = 0; kb < 4; ++kb) {
            stage_w(ws, wbase + kb * KC * HID, tid);
            __syncthreads();
            warp_mma_chunk(ha, rowbase, kb * KC, ws, acc, lane);
            __syncthreads();
        }

        float* dst = half ? g_B : g_A;
        long r0 = nbase + rowbase + q;
        long r1 = r0 + 8;
        #pragma unroll
        for (int j = 0; j < 16; ++j) {
            int col = j * 8 + 2 * m;
            if (r0 < (long)N) {
                dst[r0 * HID + col]     = acc[j][0];
                dst[r0 * HID + col + 1] = acc[j][1];
            }
            if (r1 < (long)N) {
                dst[r1 * HID + col]     = acc[j][2];
                dst[r1 * HID + col + 1] = acc[j][3];
            }
        }
    }
}

// ---------------------------------------------------------------------------
// Edge kernel: m1 = silu(A[s] + B[t] + d*w1d + b1)   (gather-add, SIMT)
//              m2 = silu(m1 @ w2 + b2)               (tf32 MMA)
//              g  = sigmoid(m2 . winf + binf)        (fragment dot + quad shfl)
//              g_mi[s] += g * m2                     (red.v4)
// ---------------------------------------------------------------------------
__global__ void __launch_bounds__(TPB, 4)
edge_kernel(const float* __restrict__ x, const int* __restrict__ edges,
            const float* __restrict__ w1, const float* __restrict__ b1,
            const float* __restrict__ w2, const float* __restrict__ b2,
            const float* __restrict__ winf, const float* __restrict__ binf,
            int N, int E) {
    extern __shared__ float sm[];
    float* hs = sm;                                 // EB*STR : A[s]+B[t] -> m1 -> m2
    uint32_t* ws = (uint32_t*)(hs + EB * STR);      // KC*HID
    float* s_wi = (float*)(ws + KC * HID);          // HID
    float* s_b2 = s_wi + HID;                       // HID
    float* s_gd = s_b2 + HID;                       // EB : dist
    float* s_g  = s_gd + EB;                        // EB : gate
    int*   s_st = (int*)(s_g + EB);                 // EB
    int*   s_en = s_st + EB;                        // EB

    const int tid = threadIdx.x;
    const int lane = tid & 31, warp = tid >> 5;
    const int rowbase = warp * 16;
    const int m = lane & 3, q = lane >> 2;
    const long ebase = (long)blockIdx.x * EB;

    if (tid < HID) { s_wi[tid] = winf[tid]; s_b2[tid] = b2[tid]; }

    if (tid < EB) {
        long e = ebase + tid;
        int st = -1, en = -1; float d = 0.f;
        if (e < (long)E) {
            st = edges[2 * e];
            en = edges[2 * e + 1];
            float dx = x[3 * st + 0] - x[3 * en + 0];
            float dy = x[3 * st + 1] - x[3 * en + 1];
            float dz = x[3 * st + 2] - x[3 * en + 2];
            d = sqrtf(dx * dx + dy * dy + dz * dz);
        }
        s_st[tid] = st; s_en[tid] = en; s_gd[tid] = d;
    }
    __syncthreads();

    // gather A[src] + B[dst]
    for (int i = tid; i < EB * 32; i += TPB) {
        int row = i >> 5, c4 = i & 31;
        int rs = s_st[row], rt = s_en[row];
        float4 v = make_float4(0.f, 0.f, 0.f, 0.f);
        if (rs >= 0) {
            float4 a = ((const float4*)(g_A + (long)rs * HID))[c4];
            float4 b = ((const float4*)(g_B + (long)rt * HID))[c4];
            v = make_float4(a.x + b.x, a.y + b.y, a.z + b.z, a.w + b.w);
        }
        ((float4*)(hs + row * STR))[c4] = v;
    }
    __syncthreads();

    // m1 = silu(hs + d*w1d + b1); each thread owns column tid across all rows
    {
        float wr = w1[256 * HID + tid];
        float bb = b1[tid];
        for (int t = 0; t < EB; ++t) {
            float v = fmaf(s_gd[t], wr, hs[t * STR + tid]) + bb;
            hs[t * STR + tid] = silu_f(v);
        }
    }
    __syncthreads();

    // layer 2: m2 = m1 @ w2 (tf32 MMA)
    float acc[16][4];
    #pragma unroll
    for (int j = 0; j < 16; ++j)
        #pragma unroll
        for (int t = 0; t < 4; ++t) acc[j][t] = 0.f;

    for (int kb = 0; kb < 4; ++kb) {
        stage_w(ws, w2 + kb * KC * HID, tid);
        __syncthreads();
        warp_mma_chunk(hs, rowbase, kb * KC, ws, acc, lane);
        __syncthreads();
    }

    // bias + silu + gate partial dot in fragments
    float p0 = 0.f, p1 = 0.f;
    #pragma unroll
    for (int j = 0; j < 16; ++j) {
        int col = j * 8 + 2 * m;
        float b0v = s_b2[col], b1v = s_b2[col + 1];
        acc[j][0] = silu_f(acc[j][0] + b0v);
        acc[j][1] = silu_f(acc[j][1] + b1v);
        acc[j][2] = silu_f(acc[j][2] + b0v);
        acc[j][3] = silu_f(acc[j][3] + b1v);
        float w0v = s_wi[col], w1v = s_wi[col + 1];
        p0 = fmaf(acc[j][0], w0v, fmaf(acc[j][1], w1v, p0));
        p1 = fmaf(acc[j][2], w0v, fmaf(acc[j][3], w1v, p1));
    }
    p0 += __shfl_xor_sync(0xffffffffu, p0, 1);
    p0 += __shfl_xor_sync(0xffffffffu, p0, 2);
    p1 += __shfl_xor_sync(0xffffffffu, p1, 1);
    p1 += __shfl_xor_sync(0xffffffffu, p1, 2);
    float bi = binf[0];
    if (m == 0) {
        s_g[rowbase + q]     = 1.f / (1.f + __expf(-(p0 + bi)));
        s_g[rowbase + q + 8] = 1.f / (1.f + __expf(-(p1 + bi)));
    }

    // store m2 fragments back to hs (own rows only)
    #pragma unroll
    for (int j = 0; j < 16; ++j) {
        int col = j * 8 + 2 * m;
        float* r0 = hs + (rowbase + q) * STR + col;
        r0[0] = acc[j][0];
        r0[1] = acc[j][1];
        r0[8 * STR]     = acc[j][2];
        r0[8 * STR + 1] = acc[j][3];
    }
    __syncthreads();

    // scatter: g_mi[src] += g * m2 ; 2 threads per row, 64 cols each
    {
        int row = tid >> 1, hc = (tid & 1) * 64;
        int st = s_st[row];
        if (st >= 0) {
            float g = s_g[row];
            const float4* srcr = (const float4*)(hs + row * STR + hc);
            float* dst = g_mi + (long)st * HID + hc;
            #pragma unroll
            for (int c4 = 0; c4 < 16; ++c4) {
                float4 v = srcr[c4];
                red_add_v4(dst + c4 * 4, g * v.x, g * v.y, g * v.z, g * v.w);
            }
        }
    }
}

// ---------------------------------------------------------------------------
// Node kernel: h_new = h + (silu([h|m_i] @ wh1 + bh1) @ wh2 + bh2)
// One 64xSTR buffer reused: h -> m_i -> u1.
// ---------------------------------------------------------------------------
__global__ void __launch_bounds__(TPB, 4)
node_kernel(const float* __restrict__ h,
            const float* __restrict__ wh1, const float* __restrict__ bh1,
            const float* __restrict__ wh2, const float* __restrict__ bh2,
            float* __restrict__ out, int N) {
    extern __shared__ float sm[];
    float* ha = sm;                                 // EB*STR
    uint32_t* ws = (uint32_t*)(ha + EB * STR);      // KC*HID
    float* s_b1 = (float*)(ws + KC * HID);          // HID
    float* s_b2 = s_b1 + HID;                       // HID

    const int tid = threadIdx.x;
    const int lane = tid & 31, warp = tid >> 5;
    const int rowbase = warp * 16;
    const int m = lane & 3, q = lane >> 2;
    const long nbase = (long)blockIdx.x * EB;

    if (tid < HID) { s_b1[tid] = bh1[tid]; s_b2[tid] = bh2[tid]; }

    for (int i = tid; i < EB * 32; i += TPB) {
        int row = i >> 5, c4 = i & 31;
        long n = nbase + row;
        float4 v = make_float4(0.f, 0.f, 0.f, 0.f);
        if (n < (long)N) v = ((const float4*)(h + n * HID))[c4];
        ((float4*)(ha + row * STR))[c4] = v;
    }
    __syncthreads();

    float acc[16][4];
    #pragma unroll
    for (int j = 0; j < 16; ++j)
        #pragma unroll
        for (int t = 0; t < 4; ++t) acc[j][t] = 0.f;

    // layer 1, k 0..127 from h
    for (int kb = 0; kb < 4; ++kb) {
        stage_w(ws, wh1 + kb * KC * HID, tid);
        __syncthreads();
        warp_mma_chunk(ha, rowbase, kb * KC, ws, acc, lane);
        __syncthreads();
    }
    // swap buffer: load m_i
    for (int i = tid; i < EB * 32; i += TPB) {
        int row = i >> 5, c4 = i & 31;
        long n = nbase + row;
        float4 v = make_float4(0.f, 0.f, 0.f, 0.f);
        if (n < (long)N) v = ((const float4*)(g_mi + n * HID))[c4];
        ((float4*)(ha + row * STR))[c4] = v;
    }
    __syncthreads();
    // layer 1, k 128..255 from m_i
    for (int kb = 4; kb < 8; ++kb) {
        stage_w(ws, wh1 + kb * KC * HID, tid);
        __syncthreads();
        warp_mma_chunk(ha, rowbase, (kb - 4) * KC, ws, acc, lane);
        __syncthreads();
    }

    // u1 = silu(acc + bh1) -> ha (own rows)
    #pragma unroll
    for (int j = 0; j < 16; ++j) {
        int col = j * 8 + 2 * m;
        float b0v = s_b1[col], b1v = s_b1[col + 1];
        float* r0 = ha + (rowbase + q) * STR + col;
        r0[0] = silu_f(acc[j][0] + b0v);
        r0[1] = silu_f(acc[j][1] + b1v);
        r0[8 * STR]     = silu_f(acc[j][2] + b0v);
        r0[8 * STR + 1] = silu_f(acc[j][3] + b1v);
    }

    // layer 2
    float acc2[16][4];
    #pragma unroll
    for (int j = 0; j < 16; ++j)
        #pragma unroll
        for (int t = 0; t < 4; ++t) acc2[j][t] = 0.f;

    for (int kb = 0; kb < 4; ++kb) {
        stage_w(ws, wh2 + kb * KC * HID, tid);
        __syncthreads();   // orders u1 writes before warp-internal reads too
        warp_mma_chunk(ha, rowbase, kb * KC, ws, acc2, lane);
        __syncthreads();
    }

    // out = h + acc2 + bh2
    long r0 = nbase + rowbase + q;
    long r1 = r0 + 8;
    #pragma unroll
    for (int j = 0; j < 16; ++j) {
        int col = j * 8 + 2 * m;
        float b0v = s_b2[col], b1v = s_b2[col + 1];
        if (r0 < (long)N) {
            const float* hr = h + r0 * HID + col;
            float* orow = out + r0 * HID + col;
            orow[0] = hr[0] + acc2[j][0] + b0v;
            orow[1] = hr[1] + acc2[j][1] + b1v;
        }
        if (r1 < (long)N) {
            const float* hr = h + r1 * HID + col;
            float* orow = out + r1 * HID + col;
            orow[0] = hr[0] + acc2[j][2] + b0v;
            orow[1] = hr[1] + acc2[j][3] + b1v;
        }
    }
}

extern "C" void kernel_launch(void* const* d_in, const int* in_sizes, int n_in,
                              void* d_out, int out_size) {
    const float* h     = (const float*)d_in[0];
    const float* x     = (const float*)d_in[1];
    const int*   edges = (const int*)d_in[2];
    const float* w_e1  = (const float*)d_in[3];
    const float* b_e1  = (const float*)d_in[4];
    const float* w_e2  = (const float*)d_in[5];
    const float* b_e2  = (const float*)d_in[6];
    const float* w_inf = (const float*)d_in[7];
    const float* b_inf = (const float*)d_in[8];
    const float* w_h1  = (const float*)d_in[9];
    const float* b_h1  = (const float*)d_in[10];
    const float* w_h2  = (const float*)d_in[11];
    const float* b_h2  = (const float*)d_in[12];
    float* out = (float*)d_out;

    int N = in_sizes[0] / HID;
    int E = in_sizes[2] / 2;

    const int SMEM_P = (EB * STR + KC * HID) * 4;
    const int SMEM_E = (EB * STR + KC * HID + 2 * HID + 4 * EB) * 4;
    const int SMEM_N = (EB * STR + KC * HID + 2 * HID) * 4;
    cudaFuncSetAttribute(pre_kernel,  cudaFuncAttributeMaxDynamicSharedMemorySize, SMEM_P);
    cudaFuncSetAttribute(edge_kernel, cudaFuncAttributeMaxDynamicSharedMemorySize, SMEM_E);
    cudaFuncSetAttribute(node_kernel, cudaFuncAttributeMaxDynamicSharedMemorySize, SMEM_N);

    int n4 = (N * HID) / 4;
    zero_mi_kernel<<<(n4 + 255) / 256, 256>>>(n4);

    pre_kernel<<<(N + EB - 1) / EB, TPB, SMEM_P>>>(h, w_e1, N);

    edge_kernel<<<(E + EB - 1) / EB, TPB, SMEM_E>>>(
        x, edges, w_e1, b_e1, w_e2, b_e2, w_inf, b_inf, N, E);

    node_kernel<<<(N + EB - 1) / EB, TPB, SMEM_N>>>(
        h, w_h1, b_h1, w_h2, b_h2, out, N);
}